// round 3
// baseline (speedup 1.0000x reference)
#include <cuda_runtime.h>
#include <cstdint>

#define NN    7680
#define NASM  256
#define CAPN  30
#define BSZ   64
#define KPL   30          // candidates per lane (max nc = 930 -> ceil/32 = 30)

__device__ float g_inv_total[NN];
__device__ float g_score[BSZ][NN];

// ---- prep config ----
#define PNT 320
#define NCHUNKS 6          // 6 * (320*4) = 7680 columns
#define COLSUM_BLOCKS 24   // 24 * 320 = 7680

// ---------------------------------------------------------------------------
// Prep: blocks [0,24) compute inv_total (W_enc denominators); blocks [24,408)
// compute g_score[b] = sum of 30 W_in rows (assembly s[b]), float4-vectorized,
// deduplicated across samples sharing s[b]. All sums are of 0/1 -> exact.
// ---------------------------------------------------------------------------
__global__ __launch_bounds__(PNT)
void prep_kernel(const int* __restrict__ p, const int* __restrict__ s,
                 const float* __restrict__ W_in, const float* __restrict__ W_rec) {
    const int bid = blockIdx.x, tid = threadIdx.x;
    if (bid < COLSUM_BLOCKS) {
        int j = bid * PNT + tid;
        int a = j / CAPN;
        float tot = 0.f;
        for (int m = 0; m < NASM; ++m) {
            if (__ldg(&p[m]) == a) {
                const float* row = W_rec + (size_t)m * CAPN * NN + j;
                #pragma unroll
                for (int r = 0; r < CAPN; ++r) tot += __ldg(&row[(size_t)r * NN]);
            }
        }
        g_inv_total[j] = 1.0f / fmaxf(tot, 1e-6f);
    } else {
        int r = bid - COLSUM_BLOCKS;
        int b = r / NCHUNKS, chunk = r % NCHUNKS;
        int sb = __ldg(&s[b]);
        for (int b2 = 0; b2 < b; ++b2)
            if (__ldg(&s[b2]) == sb) return;            // duplicate sample: skip
        const float4* base =
            (const float4*)(W_in + (size_t)sb * CAPN * NN) + chunk * PNT + tid;
        float4 acc = {0.f, 0.f, 0.f, 0.f};
        #pragma unroll
        for (int rr = 0; rr < CAPN; ++rr) {
            float4 v = __ldg(&base[(size_t)rr * (NN / 4)]);
            acc.x += v.x; acc.y += v.y; acc.z += v.z; acc.w += v.w;
        }
        ((float4*)g_score[b])[chunk * PNT + tid] = acc;
    }
}

// ---------------------------------------------------------------------------
// Chase: ONE WARP per sample. All sync is __syncwarp.
// ---------------------------------------------------------------------------
__global__ __launch_bounds__(32)
void chase_kernel(const int* __restrict__ p, const int* __restrict__ s,
                  const int* __restrict__ kk, const float* __restrict__ W_rec,
                  float* __restrict__ out) {
    __shared__ int      p_sh[NASM];
    __shared__ int      active[CAPN];          // current winner neuron indices (set)
    __shared__ unsigned tmask[8];              // targeted-assembly bitmap
    __shared__ int      bases[32];             // sorted targeted assemblies
    __shared__ int      slotcnt[32];
    __shared__ int      slotlist[31 * CAPN];
    __shared__ int      hist[256];
    __shared__ int      lh[32 * 33];           // per-lane int histogram (first select)
    __shared__ int      sh_misc[4];            // [0]=T/B [1]=n_gt [3]=emit ctr
    __shared__ int      ov[NASM];

    const int lid = threadIdx.x;
    const int b   = blockIdx.x;

    #pragma unroll
    for (int i = 0; i < 8; ++i) p_sh[lid + 32 * i] = __ldg(&p[lid + 32 * i]);

    // dedup source for the precomputed W_in row-sums
    const int sb = __ldg(&s[b]);
    int bsrc = b;
    for (int b2 = 0; b2 < b; ++b2)
        if (__ldg(&s[b2]) == sb) { bsrc = b2; break; }
    const float4* scv = (const float4*)g_score[bsrc] + lid * 60;  // 240 floats/lane

    // ---- first k-WTA: scores are exact ints 0..30; 31-bin histogram ----
    #pragma unroll
    for (int i = 0; i < 33; ++i) lh[lid * 33 + i] = 0;
    __syncwarp();
    #pragma unroll
    for (int q = 0; q < 60; ++q) {
        float4 v = __ldg(&scv[q]);
        lh[lid * 33 + (int)v.x]++;
        lh[lid * 33 + (int)v.y]++;
        lh[lid * 33 + (int)v.z]++;
        lh[lid * 33 + (int)v.w]++;
    }
    __syncwarp();
    int c = 0;
    if (lid < 31) {
        #pragma unroll
        for (int l = 0; l < 32; ++l) c += lh[l * 33 + lid];
    }
    // suffix sum S(v) = #{score >= v}
    int S = c;
    #pragma unroll
    for (int off = 1; off < 32; off <<= 1) {
        int t = __shfl_down_sync(0xFFFFFFFFu, S, off);
        if (lid + off < 32) S += t;
    }
    int Snext = __shfl_down_sync(0xFFFFFFFFu, S, 1);
    if (lid == 30) Snext = 0;
    if (lid < 31 && S >= CAPN && Snext < CAPN) {
        sh_misc[0] = lid;       // threshold value T
        sh_misc[1] = Snext;     // n_gt = #{score > T}
    }
    __syncwarp();
    {
        const int T = sh_misc[0], n_gt = sh_misc[1];
        const int need_eq = CAPN - n_gt;
        int cgt = 0, ceq = 0;
        #pragma unroll
        for (int q = 0; q < 60; ++q) {
            float4 v = __ldg(&scv[q]);
            int a0 = (int)v.x, a1 = (int)v.y, a2 = (int)v.z, a3 = (int)v.w;
            cgt += (a0 > T) + (a1 > T) + (a2 > T) + (a3 > T);
            ceq += (a0 == T) + (a1 == T) + (a2 == T) + (a3 == T);
        }
        int pack = (cgt << 16) | ceq;
        int ex = pack;
        #pragma unroll
        for (int off = 1; off < 32; off <<= 1) {
            int t = __shfl_up_sync(0xFFFFFFFFu, ex, off);
            if (lid >= off) ex += t;
        }
        ex -= pack;
        int g_off = ex >> 16, e_off = ex & 0xFFFF;
        // contiguous per-lane ownership -> equal-value rank order == ascending j
        #pragma unroll
        for (int q = 0; q < 60; ++q) {
            float4 v = __ldg(&scv[q]);
            int jb = lid * 240 + q * 4;
            int vals[4] = {(int)v.x, (int)v.y, (int)v.z, (int)v.w};
            #pragma unroll
            for (int z = 0; z < 4; ++z) {
                if (vals[z] > T) active[g_off++] = jb + z;
                else if (vals[z] == T) {
                    if (e_off < need_eq) active[n_gt + e_off] = jb + z;
                    e_off++;
                }
            }
        }
    }
    __syncwarp();

    // ---- k[b] pointer-chasing steps ----
    const int steps = __ldg(&kk[b]);
    for (int t = 0; t < steps; ++t) {
        if (lid < 8) tmask[lid] = 0u;
        slotcnt[lid] = 0;
        if (lid == 0) sh_misc[3] = 0;
        __syncwarp();
        int a_i = -1;
        if (lid < CAPN) {
            a_i = p_sh[active[lid] / CAPN];
            atomicOr(&tmask[a_i >> 5], 1u << (a_i & 31));
        }
        __syncwarp();
        // fallback = smallest non-targeted assembly (exact zero-tie semantics:
        // its 30 columns are the globally smallest-index guaranteed-zero cols)
        if (lid == 0) {
            #pragma unroll
            for (int w = 0; w < 8; ++w) {
                unsigned m = tmask[w];
                if (m != 0xFFFFFFFFu) { tmask[w] = m | (1u << (__ffs(~m) - 1)); break; }
            }
        }
        __syncwarp();
        unsigned mw[8];
        #pragma unroll
        for (int w = 0; w < 8; ++w) mw[w] = tmask[w];
        int nb = 0;
        #pragma unroll
        for (int w = 0; w < 8; ++w) nb += __popc(mw[w]);
        if (lid < nb) {                       // bases[lid] = lid-th set bit
            int rem = lid, base = -1;
            #pragma unroll
            for (int w = 0; w < 8; ++w) {
                int pc = __popc(mw[w]);
                if (base < 0) {
                    if (rem < pc) {
                        unsigned x = mw[w];
                        for (int k2 = 0; k2 < rem; ++k2) x &= x - 1;
                        base = w * 32 + __ffs(x) - 1;
                    } else rem -= pc;
                }
            }
            bases[lid] = base;
        }
        if (lid < CAPN) {                     // per-slot active lists
            int w = a_i >> 5, bit = a_i & 31;
            int slot = __popc(mw[w] & ((bit == 31) ? 0x7FFFFFFFu : ((1u << bit) - 1u)));
            #pragma unroll
            for (int ww = 0; ww < 8; ++ww) if (ww < w) slot += __popc(mw[ww]);
            int idx = atomicAdd(&slotcnt[slot], 1);
            slotlist[slot * CAPN + idx] = active[lid];
        }
        __syncwarp();
        const int nc = nb * CAPN;             // 60..930

        // gather: cnt[e] = #active synapses into column j(e); exactly 900 LDGs
        unsigned long long key[KPL];
        #pragma unroll
        for (int q = 0; q < KPL; ++q) {
            int e = lid + 32 * q;
            key[q] = 0ull;
            if (e < nc) {
                int slot = e / CAPN, cc = e - slot * CAPN;
                int j = bases[slot] * CAPN + cc;
                int m = slotcnt[slot];
                int cnt = 0;
                for (int u = 0; u < m; ++u) {
                    int i = slotlist[slot * CAPN + u];
                    cnt += (__ldg(&W_rec[(size_t)i * NN + j]) != 0.f);
                }
                // cnt * inv preserves exact order & tie classes of the ref sums
                float sc = (float)cnt * g_inv_total[j];
                key[q] = ((unsigned long long)__float_as_uint(sc) << 32) |
                         (unsigned)(~e);
            }
        }
        // coarse 256-bin histogram on sc in [0,1]
        #pragma unroll
        for (int i = 0; i < 8; ++i) hist[lid * 8 + i] = 0;
        __syncwarp();
        #pragma unroll
        for (int q = 0; q < KPL; ++q) {
            if (key[q]) {
                float v = __uint_as_float((unsigned)(key[q] >> 32));
                atomicAdd(&hist[min(255, (int)(v * 256.0f))], 1);
            }
        }
        __syncwarp();
        int hv[8], ls = 0;
        #pragma unroll
        for (int i = 0; i < 8; ++i) { hv[i] = hist[lid * 8 + i]; ls += hv[i]; }
        int Suf = ls;
        #pragma unroll
        for (int off = 1; off < 32; off <<= 1) {
            int tt = __shfl_down_sync(0xFFFFFFFFu, Suf, off);
            if (lid + off < 32) Suf += tt;
        }
        {
            int acc = Suf - ls;               // #{bin > my top bin}
            #pragma unroll
            for (int i = 7; i >= 0; --i) {
                int Sb = acc + hv[i];
                if (Sb >= CAPN && acc < CAPN) { sh_misc[0] = lid * 8 + i; sh_misc[1] = acc; }
                acc = Sb;
            }
        }
        __syncwarp();
        const int B = sh_misc[0], n_gt = sh_misc[1];
        const int k_rem = CAPN - n_gt;
        // emit bins > B (unordered: kWTA result is a set); keep ==B for rounds
        unsigned long long lmax = 0ull;
        #pragma unroll
        for (int q = 0; q < KPL; ++q) {
            if (key[q]) {
                float v = __uint_as_float((unsigned)(key[q] >> 32));
                int bin = min(255, (int)(v * 256.0f));
                if (bin > B) {
                    int pos = atomicAdd(&sh_misc[3], 1);
                    int e = ~(unsigned)key[q];
                    active[pos] = bases[e / CAPN] * CAPN + (e - (e / CAPN) * CAPN);
                    key[q] = 0ull;
                } else if (bin < B) key[q] = 0ull;
                else lmax = max(lmax, key[q]);
            }
        }
        __syncwarp();
        // exact (value desc, index asc) rounds for the threshold bin
        for (int r2 = 0; r2 < k_rem; ++r2) {
            unsigned Mhi = __reduce_max_sync(0xFFFFFFFFu, (unsigned)(lmax >> 32));
            unsigned lo  = ((unsigned)(lmax >> 32) == Mhi) ? (unsigned)lmax : 0u;
            unsigned Mlo = __reduce_max_sync(0xFFFFFFFFu, lo);
            unsigned long long wk = ((unsigned long long)Mhi << 32) | Mlo;
            if (lmax == wk) {                 // exactly one winner lane
                int e = (int)(~Mlo);
                active[n_gt + r2] = bases[e / CAPN] * CAPN + (e - (e / CAPN) * CAPN);
                #pragma unroll
                for (int q = 0; q < KPL; ++q) if (key[q] == wk) key[q] = 0ull;
                lmax = 0ull;
                #pragma unroll
                for (int q = 0; q < KPL; ++q) lmax = max(lmax, key[q]);
            }
        }
        __syncwarp();
    }

    // ---- overlaps + first-max argmax + one-hot ----
    #pragma unroll
    for (int i = 0; i < 8; ++i) ov[lid * 8 + i] = 0;
    __syncwarp();
    if (lid < CAPN) atomicAdd(&ov[active[lid] / CAPN], 1);
    __syncwarp();
    unsigned bk = 0;
    #pragma unroll
    for (int i = 0; i < 8; ++i) {
        int a2 = lid * 8 + i;
        bk = max(bk, (unsigned)((ov[a2] << 8) | (255 - a2)));
    }
    bk = __reduce_max_sync(0xFFFFFFFFu, bk);
    const int best = 255 - (int)(bk & 255u);
    #pragma unroll
    for (int i = 0; i < 8; ++i)
        out[b * NASM + lid * 8 + i] = (lid * 8 + i == best) ? 1.0f : 0.0f;
}

// ---------------------------------------------------------------------------
extern "C" void kernel_launch(void* const* d_in, const int* in_sizes, int n_in,
                              void* d_out, int out_size) {
    const int*   p     = (const int*)d_in[0];   // [256]
    const int*   s     = (const int*)d_in[1];   // [64]
    const int*   kk    = (const int*)d_in[2];   // [64]
    const float* W_in  = (const float*)d_in[3]; // [7680,7680]
    const float* W_rec = (const float*)d_in[4]; // [7680,7680]
    float* out = (float*)d_out;                 // [64,256]

    prep_kernel<<<COLSUM_BLOCKS + BSZ * NCHUNKS, PNT>>>(p, s, W_in, W_rec);
    chase_kernel<<<BSZ, 32>>>(p, s, kk, W_rec, out);
}

// round 4
// speedup vs baseline: 2.0664x; 2.0664x over previous
#include <cuda_runtime.h>
#include <cstdint>

#define NN    7680
#define NASM  256
#define CAPN  30
#define BSZ   64
#define NT    256
#define MAXC  960          // >= max candidates (31 assemblies * 30)

typedef unsigned long long ull;

__device__ float g_inv_total[NN];
__device__ float g_score[BSZ][NN];

// ---- prep config ----
#define PNT 320
#define NCHUNKS 6          // 6 * (320*4) = 7680 columns
#define COLSUM_BLOCKS 24   // 24 * 320 = 7680

// ---------------------------------------------------------------------------
// Prep: blocks [0,24) -> inv_total (W_enc denominators); blocks [24,408) ->
// g_score[b] = sum of 30 W_in rows (assembly s[b]), float4, deduped across
// samples sharing s[b]. Sums of 0/1 values are exact & order-independent.
// ---------------------------------------------------------------------------
__global__ __launch_bounds__(PNT)
void prep_kernel(const int* __restrict__ p, const int* __restrict__ s,
                 const float* __restrict__ W_in, const float* __restrict__ W_rec) {
    const int bid = blockIdx.x, tid = threadIdx.x;
    if (bid < COLSUM_BLOCKS) {
        int j = bid * PNT + tid;
        int a = j / CAPN;
        float tot = 0.f;
        for (int m = 0; m < NASM; ++m) {
            if (__ldg(&p[m]) == a) {
                const float* row = W_rec + (size_t)m * CAPN * NN + j;
                #pragma unroll
                for (int r = 0; r < CAPN; ++r) tot += __ldg(&row[(size_t)r * NN]);
            }
        }
        g_inv_total[j] = 1.0f / fmaxf(tot, 1e-6f);
    } else {
        int r = bid - COLSUM_BLOCKS;
        int b = r / NCHUNKS, chunk = r % NCHUNKS;
        int sb = __ldg(&s[b]);
        for (int b2 = 0; b2 < b; ++b2)
            if (__ldg(&s[b2]) == sb) return;            // duplicate sample
        const float4* base =
            (const float4*)(W_in + (size_t)sb * CAPN * NN) + chunk * PNT + tid;
        float4 acc = {0.f, 0.f, 0.f, 0.f};
        #pragma unroll
        for (int rr = 0; rr < CAPN; ++rr) {
            float4 v = __ldg(&base[(size_t)rr * (NN / 4)]);
            acc.x += v.x; acc.y += v.y; acc.z += v.z; acc.w += v.w;
        }
        ((float4*)g_score[b])[chunk * PNT + tid] = acc;
    }
}

// ---------------------------------------------------------------------------
// Block-wide inclusive scan (256 threads). Ends with a barrier.
// ---------------------------------------------------------------------------
__device__ __forceinline__ int block_scan_incl(int v, int* wsum, int tid) {
    int lane = tid & 31, w = tid >> 5;
    int x = v;
    #pragma unroll
    for (int off = 1; off < 32; off <<= 1) {
        int n = __shfl_up_sync(0xFFFFFFFFu, x, off);
        if (lane >= off) x += n;
    }
    if (lane == 31) wsum[w] = x;
    __syncthreads();
    if (tid < 8) {
        int y = wsum[tid];
        #pragma unroll
        for (int off = 1; off < 8; off <<= 1) {
            int n = __shfl_up_sync(0xFFu, y, off);
            if (tid >= off) y += n;
        }
        wsum[tid] = y;
    }
    __syncthreads();
    int r = x + (w ? wsum[w - 1] : 0);
    __syncthreads();
    return r;
}

// ---------------------------------------------------------------------------
// Chase: one 256-thread block per sample.
// ---------------------------------------------------------------------------
__global__ __launch_bounds__(NT)
void chase_kernel(const int* __restrict__ p, const int* __restrict__ s,
                  const int* __restrict__ kk, const float* __restrict__ W_rec,
                  float* __restrict__ out) {
    __shared__ alignas(16) float score_sh[NN];  // 30 KB; later aliased:
    //   keys = (ull*)score_sh           bytes [0, 7680)    (960 x u64)
    //   cnt  = (int*)(score_sh + 4000)  bytes [16000, 19840)
    __shared__ int      hist[256];
    __shared__ int      wsum[8];
    __shared__ int      p_sh[NASM];
    __shared__ int      active[CAPN];
    __shared__ unsigned tmask[8];
    __shared__ int      bases[32];
    __shared__ int      slot_of[NASM];
    __shared__ int      sh[4];      // [0]=threshold [1]=n_gt [2]=emit ctr [3]=nb
    __shared__ int      ov[NASM];

    const int tid = threadIdx.x;
    const int b   = blockIdx.x;

    if (tid < NASM) p_sh[tid] = __ldg(&p[tid]);
    // dedup source for the precomputed W_in row-sums
    const int sb = __ldg(&s[b]);
    int bsrc = b;
    for (int b2 = 0; b2 < b; ++b2)
        if (__ldg(&s[b2]) == sb) { bsrc = b2; break; }
    #pragma unroll
    for (int c2 = 0; c2 < NN / NT; ++c2)
        score_sh[tid + c2 * NT] = g_score[bsrc][tid + c2 * NT];
    if (tid < 32) hist[tid] = 0;
    __syncthreads();

    // ---- first k-WTA: scores are exact ints 0..30 -> 31-bin histogram ----
    // Thread t owns columns [t*30, t*30+30): contiguous -> exact tie order.
    for (int q = 0; q < CAPN; ++q)
        atomicAdd(&hist[(int)score_sh[tid * CAPN + q]], 1);
    __syncthreads();
    if (tid < 32) {
        int tot = (tid < 31) ? hist[tid] : 0;
        int S = tot;                              // suffix sum: #{score >= tid}
        #pragma unroll
        for (int off = 1; off < 32; off <<= 1) {
            int tp = __shfl_down_sync(0xFFFFFFFFu, S, off);
            if (tid + off < 32) S += tp;
        }
        if (tid < 31 && S >= CAPN && S - tot < CAPN) {
            sh[0] = tid;                          // threshold value T
            sh[1] = S - tot;                      // n_gt = #{score > T}
        }
    }
    __syncthreads();
    {
        const int T = sh[0], n_gt = sh[1], need_eq = CAPN - n_gt;
        int cgt = 0, ceq = 0;
        for (int q = 0; q < CAPN; ++q) {
            int val = (int)score_sh[tid * CAPN + q];
            cgt += (val > T); ceq += (val == T);
        }
        int pack = (cgt << 16) | ceq;
        int ex = block_scan_incl(pack, wsum, tid) - pack;
        int g_off = ex >> 16, e_off = ex & 0xFFFF;
        for (int q = 0; q < CAPN; ++q) {
            int j = tid * CAPN + q;
            int val = (int)score_sh[j];
            if (val > T) active[g_off++] = j;
            else if (val == T) {
                if (e_off < need_eq) active[n_gt + e_off] = j;
                e_off++;
            }
        }
    }
    __syncthreads();

    // ---- k[b] pointer-chasing steps ----
    ull* keys = (ull*)score_sh;
    int* cnt  = (int*)(score_sh + 4000);
    const int steps = __ldg(&kk[b]);
    for (int t = 0; t < steps; ++t) {
        if (tid < 8) tmask[tid] = 0u;
        if (tid == 0) sh[2] = 0;
        __syncthreads();
        if (tid < CAPN) {
            int a = p_sh[active[tid] / CAPN];
            atomicOr(&tmask[a >> 5], 1u << (a & 31));
        }
        __syncthreads();
        // fallback = smallest non-targeted assembly: its 30 columns are the
        // smallest-index guaranteed-zero columns (exact zero-tie semantics)
        if (tid == 0) {
            #pragma unroll
            for (int w = 0; w < 8; ++w) {
                unsigned m = tmask[w];
                if (m != 0xFFFFFFFFu) { tmask[w] = m | (1u << (__ffs(~m) - 1)); break; }
            }
        }
        __syncthreads();
        if (tid < 32) {
            unsigned mw[8];
            #pragma unroll
            for (int w = 0; w < 8; ++w) mw[w] = tmask[w];
            int nb = 0;
            #pragma unroll
            for (int w = 0; w < 8; ++w) nb += __popc(mw[w]);
            if (tid == 0) sh[3] = nb;
            if (tid < nb) {                       // tid-th set bit, ascending
                int rem = tid, base = -1;
                #pragma unroll
                for (int w = 0; w < 8; ++w) {
                    int pc = __popc(mw[w]);
                    if (base < 0) {
                        if (rem < pc) {
                            unsigned x = mw[w];
                            for (int k2 = 0; k2 < rem; ++k2) x &= x - 1;
                            base = w * 32 + __ffs(x) - 1;
                        } else rem -= pc;
                    }
                }
                bases[tid] = base;
                slot_of[base] = tid;
            }
        }
        __syncthreads();
        const int nb = sh[3], nc = nb * CAPN;     // 60..930
        for (int e = tid; e < nc; e += NT) cnt[e] = 0;
        hist[tid] = 0;
        __syncthreads();

        // gather: 900 independent scattered loads across 256 threads.
        // Integer counts -> order-independent.
        for (int e2 = tid; e2 < CAPN * CAPN; e2 += NT) {
            int x = e2 / CAPN, c = e2 - x * CAPN;
            int i = active[x];
            int a = p_sh[i / CAPN];
            if (__ldg(&W_rec[(size_t)i * NN + a * CAPN + c]) != 0.f)
                atomicAdd(&cnt[slot_of[a] * CAPN + c], 1);
        }
        __syncthreads();

        // keys + coarse 256-bin histogram (bin width 1/256 < min score gap
        // except at exact ties -> threshold bin holds the exact-tie frontier)
        for (int e = tid; e < nc; e += NT) {
            int j = bases[e / CAPN] * CAPN + (e - (e / CAPN) * CAPN);
            float sc = (float)cnt[e] * g_inv_total[j];   // == ref column sum
            keys[e] = ((ull)__float_as_uint(sc) << 32) | (unsigned)(~e);
            atomicAdd(&hist[min(255, (int)(sc * 256.f))], 1);
        }
        __syncthreads();
        {   // suffix scan over bins: thread tid handles bin 255-tid
            int tot = hist[255 - tid];
            int S = block_scan_incl(tot, wsum, tid);     // #{bin >= 255-tid}
            if (S >= CAPN && S - tot < CAPN) { sh[0] = 255 - tid; sh[1] = S - tot; }
        }
        __syncthreads();
        const int B = sh[0], ngt = sh[1], k_rem = CAPN - ngt;
        // emit bins > B (unordered: kWTA result is a set); zero everything
        // except the threshold bin
        for (int e = tid; e < nc; e += NT) {
            float scv = __uint_as_float((unsigned)(keys[e] >> 32));
            int bin = min(255, (int)(scv * 256.f));
            if (bin > B) {
                int pos = atomicAdd(&sh[2], 1);
                active[pos] = bases[e / CAPN] * CAPN + (e - (e / CAPN) * CAPN);
                keys[e] = 0ull;
            } else if (bin < B) keys[e] = 0ull;
        }
        __syncthreads();
        // warp 0: exact (value desc, index asc) rounds for the threshold bin
        if (tid < 32) {
            for (int r2 = 0; r2 < k_rem; ++r2) {
                ull lmax = 0ull;
                for (int e = tid; e < nc; e += 32) lmax = max(lmax, keys[e]);
                unsigned Mhi = __reduce_max_sync(0xFFFFFFFFu, (unsigned)(lmax >> 32));
                unsigned lo  = ((unsigned)(lmax >> 32) == Mhi) ? (unsigned)lmax : 0u;
                unsigned Mlo = __reduce_max_sync(0xFFFFFFFFu, lo);
                if ((unsigned)(lmax >> 32) == Mhi && (unsigned)lmax == Mlo) {
                    int e = (int)(~Mlo);
                    active[ngt + r2] = bases[e / CAPN] * CAPN + (e - (e / CAPN) * CAPN);
                    keys[e] = 0ull;
                }
                __syncwarp();
            }
        }
        __syncthreads();
    }

    // ---- overlaps + first-max argmax + one-hot ----
    ov[tid] = 0;
    if (tid == 0) sh[0] = -1;
    __syncthreads();
    if (tid < CAPN) atomicAdd(&ov[active[tid] / CAPN], 1);
    __syncthreads();
    atomicMax(&sh[0], (ov[tid] << 8) | (255 - tid));   // ties -> smallest id
    __syncthreads();
    const int best = 255 - (sh[0] & 255);
    out[b * NASM + tid] = (tid == best) ? 1.0f : 0.0f;
}

// ---------------------------------------------------------------------------
extern "C" void kernel_launch(void* const* d_in, const int* in_sizes, int n_in,
                              void* d_out, int out_size) {
    const int*   p     = (const int*)d_in[0];   // [256]
    const int*   s     = (const int*)d_in[1];   // [64]
    const int*   kk    = (const int*)d_in[2];   // [64]
    const float* W_in  = (const float*)d_in[3]; // [7680,7680]
    const float* W_rec = (const float*)d_in[4]; // [7680,7680]
    float* out = (float*)d_out;                 // [64,256]

    prep_kernel<<<COLSUM_BLOCKS + BSZ * NCHUNKS, PNT>>>(p, s, W_in, W_rec);
    chase_kernel<<<BSZ, NT>>>(p, s, kk, W_rec, out);
}